// round 5
// baseline (speedup 1.0000x reference)
#include <cuda_runtime.h>
#include <cstdint>

// RWKV7 chunked attention, B=4 T=2048 H=32 C=64 dT=16.
// Two-kernel split:
//   k1 (parallel over all 16384 (bh,chunk) tiles): grams AB/QB + AKV=ak@v, QKV=qk@v
//   k2 (sequential scan, 4 CTAs per bh splitting the i dimension): state GEMM,
//      triangular solve, y, state update.

#define B_ 4
#define T_ 2048
#define H_ 32
#define C_ 64
#define DT_ 16
#define NT_ 128
#define SPLIT 4
#define CI 16

typedef unsigned long long u64;

// scratch per (bh,ch): AB[256] QB[256] AKV[16][64] QKV[16][64] = 2560 floats
#define SCR_STRIDE 2560
__device__ float g_scr[(size_t)B_ * H_ * NT_ * SCR_STRIDE];

__device__ __forceinline__ int tile_w(int row, int c) {   // scalar slot in [16][64] xor-swizzled tile
    return row * 64 + ((((c >> 2) ^ row) & 15) << 2) + (c & 3);
}
__device__ __forceinline__ int tile_off(int row, int f) { // float4-group slot
    return row * 64 + (((f ^ row) & 15) << 2);
}

__device__ __forceinline__ float4 ld4(const float* p) { return *reinterpret_cast<const float4*>(p); }
__device__ __forceinline__ void st4(float* p, float4 v) { *reinterpret_cast<float4*>(p) = v; }
__device__ __forceinline__ ulonglong2 ldp(const float* p) { return *reinterpret_cast<const ulonglong2*>(p); }
__device__ __forceinline__ void stp(float* p, ulonglong2 v) { *reinterpret_cast<ulonglong2*>(p) = v; }

__device__ __forceinline__ u64 pk2(float lo, float hi) {
    u64 r; asm("mov.b64 %0, {%1, %2};" : "=l"(r) : "f"(lo), "f"(hi)); return r;
}
__device__ __forceinline__ void un2(u64 v, float& lo, float& hi) {
    asm("mov.b64 {%0, %1}, %2;" : "=f"(lo), "=f"(hi) : "l"(v));
}
__device__ __forceinline__ void fma2(u64& d, u64 a, u64 b) {
    asm("fma.rn.f32x2 %0, %1, %2, %0;" : "+l"(d) : "l"(a), "l"(b));
}
__device__ __forceinline__ u64 add2(u64 a, u64 b) {
    u64 d; asm("add.rn.f32x2 %0, %1, %2;" : "=l"(d) : "l"(a), "l"(b)); return d;
}
__device__ __forceinline__ u64 mul2(u64 a, u64 b) {
    u64 d; asm("mul.rn.f32x2 %0, %1, %2;" : "=l"(d) : "l"(a), "l"(b)); return d;
}

// ===================== Kernel 1: chunk-local precompute =====================
__global__ __launch_bounds__(128, 6)
void rwkv7_pre(const float* __restrict__ gw, const float* __restrict__ gq,
               const float* __restrict__ gk, const float* __restrict__ gv,
               const float* __restrict__ ga, const float* __restrict__ gb)
{
    __shared__ __align__(16) float sWA[1024], sWQ[1024], sKWI[1024], sBWI[1024], sV[1024];
    __shared__ __align__(16) float sLP[2][64];
    __shared__ __align__(16) float sAB[256], sQB[256], sAKQK[512];

    const int bid = blockIdx.x;
    const int bh = bid >> 7, ch = bid & 127;
    const int b = bh / H_, h = bh % H_;
    const int tid = threadIdx.x;
    const int th = tid >> 6, cl = tid & 63;
    const size_t strT = (size_t)H_ * C_;

    // ---- load + decay + stage ----
    {
        size_t base = (((size_t)b * T_ + ch * DT_ + th * 8) * H_ + h) * C_ + cl;
        float rw[8], rq[8], rk[8], rv[8], ra[8], rb[8];
        #pragma unroll
        for (int r = 0; r < 8; r++) {
            size_t ix = base + (size_t)r * strT;
            rw[r] = gw[ix]; rq[r] = gq[ix]; rk[r] = gk[ix];
            rv[r] = gv[ix]; ra[r] = ga[ix]; rb[r] = gb[ix];
        }
        float wd[8]; float lp = 1.f;
        #pragma unroll
        for (int r = 0; r < 8; r++) { wd[r] = __expf(-__expf(rw[r])); lp *= wd[r]; }
        sLP[th][cl] = lp;
        __syncthreads();
        float incl = th ? sLP[0][cl] : 1.f;
        #pragma unroll
        for (int r = 0; r < 8; r++) {
            int t = th * 8 + r;
            float ip = incl; incl *= wd[r];
            float rinv = __fdividef(1.f, incl);
            int twd = tile_w(t, cl);
            sWQ[twd]  = rq[r] * incl;
            sWA[twd]  = ra[r] * ip;
            sKWI[twd] = rk[r] * rinv;
            sBWI[twd] = rb[r] * rinv;
            sV[twd]   = rv[r];
        }
    }
    __syncthreads();

    // ---- grams: thread (t = tid>>3) handles s = (tid&7) and (tid&7)+8 ----
    {
        const int t = tid >> 3, sb = tid & 7;
        #pragma unroll
        for (int sh = 0; sh < 2; sh++) {
            const int s = sb + 8 * sh;
            u64 ab2 = 0, ak2 = 0, qb2 = 0, qk2 = 0;
            #pragma unroll
            for (int c4 = 0; c4 < 16; c4++) {
                ulonglong2 A  = ldp(sWA  + t * 64 + (((c4 ^ t) & 15) << 2));
                ulonglong2 Q  = ldp(sWQ  + t * 64 + (((c4 ^ t) & 15) << 2));
                ulonglong2 Bv = ldp(sBWI + s * 64 + (((c4 ^ s) & 15) << 2));
                ulonglong2 Kv = ldp(sKWI + s * 64 + (((c4 ^ s) & 15) << 2));
                fma2(ab2, A.x, Bv.x); fma2(ab2, A.y, Bv.y);
                fma2(ak2, A.x, Kv.x); fma2(ak2, A.y, Kv.y);
                fma2(qb2, Q.x, Bv.x); fma2(qb2, Q.y, Bv.y);
                fma2(qk2, Q.x, Kv.x); fma2(qk2, Q.y, Kv.y);
            }
            float l, hh, ab, ak, qb, qk;
            un2(ab2, l, hh); ab = l + hh;
            un2(ak2, l, hh); ak = l + hh;
            un2(qb2, l, hh); qb = l + hh;
            un2(qk2, l, hh); qk = l + hh;
            float ms = (t > s)  ? 1.f : 0.f;
            float mi = (t >= s) ? 1.f : 0.f;
            sAB[t * 16 + s] = ab * ms;
            sQB[t * 16 + s] = qb * mi;
            sAKQK[(t * 16 + s) * 2]     = ak * ms;
            sAKQK[(t * 16 + s) * 2 + 1] = qk * mi;
        }
    }
    __syncthreads();

    // ---- AKV = ak@v, QKV = qk@v; write scratch ----
    {
        float* dst = g_scr + (size_t)(bh * NT_ + ch) * SCR_STRIDE;
        const int t = tid >> 3, io = tid & 7;      // i = 8*io .. 8*io+7
        u64 acc[8] = {0, 0, 0, 0, 0, 0, 0, 0};
        #pragma unroll
        for (int s = 0; s < 16; s++) {
            u64 akqk = *reinterpret_cast<const u64*>(sAKQK + (t * 16 + s) * 2);
            float4 va = ld4(sV + tile_off(s, 2 * io));
            float4 vb = ld4(sV + tile_off(s, 2 * io + 1));
            fma2(acc[0], akqk, pk2(va.x, va.x));
            fma2(acc[1], akqk, pk2(va.y, va.y));
            fma2(acc[2], akqk, pk2(va.z, va.z));
            fma2(acc[3], akqk, pk2(va.w, va.w));
            fma2(acc[4], akqk, pk2(vb.x, vb.x));
            fma2(acc[5], akqk, pk2(vb.y, vb.y));
            fma2(acc[6], akqk, pk2(vb.z, vb.z));
            fma2(acc[7], akqk, pk2(vb.w, vb.w));
        }
        float akv[8], qkv[8];
        #pragma unroll
        for (int j = 0; j < 8; j++) un2(acc[j], akv[j], qkv[j]);
        st4(dst + 512  + t * 64 + 8 * io,     make_float4(akv[0], akv[1], akv[2], akv[3]));
        st4(dst + 512  + t * 64 + 8 * io + 4, make_float4(akv[4], akv[5], akv[6], akv[7]));
        st4(dst + 1536 + t * 64 + 8 * io,     make_float4(qkv[0], qkv[1], qkv[2], qkv[3]));
        st4(dst + 1536 + t * 64 + 8 * io + 4, make_float4(qkv[4], qkv[5], qkv[6], qkv[7]));
        // AB | QB contiguous 512 floats
        st4(dst + tid * 4, ld4((tid < 64 ? sAB + tid * 4 : sQB + (tid - 64) * 4)));
    }
}

// ===================== Kernel 2: sequential scan, i-split =====================
__global__ __launch_bounds__(128, 4)
void rwkv7_scan(const float* __restrict__ gw, const float* __restrict__ gq,
                const float* __restrict__ gk, const float* __restrict__ gv,
                const float* __restrict__ ga, const float* __restrict__ gb,
                const float* __restrict__ gs0, float* __restrict__ gy)
{
    __shared__ __align__(16) float sWA[1024], sWQ[1024], sKWI[1024], sBWI[1024];
    __shared__ __align__(16) float sS[1024];                 // [16 i][64 j] swizzled
    __shared__ __align__(16) float sV[256], sU[256], sABU[256], sAKV[256], sQKV[256];
    __shared__ __align__(16) float sGR[512];                 // AB [0:256) | QB [256:512)
    __shared__ __align__(16) float sLP[2][64], sFW[64];

    const int bid = blockIdx.x;
    const int bh = bid >> 2, isp = bid & 3;
    const int b = bh / H_, h = bh % H_;
    const int i0 = isp * CI;
    const int tid = threadIdx.x;
    const int th = tid >> 6, cl = tid & 63;
    const size_t strT = (size_t)H_ * C_;
    const float* scr = g_scr + (size_t)bh * NT_ * SCR_STRIDE;
    const bool mine = (cl >> 4) == isp;

    // init state slice
    {
        const float* s0p = gs0 + (size_t)bh * 4096 + (size_t)i0 * 64;
        for (int q4 = tid; q4 < 256; q4 += 128) {
            int il = q4 >> 4, f = q4 & 15;
            st4(sS + il * 64 + (((f ^ il) & 15) << 2), ld4(s0p + il * 64 + f * 4));
        }
    }
    __syncthreads();

    for (int ch = 0; ch < NT_; ch++) {
        // ===== stage: raw loads, scratch loads, decay =====
        {
            const float* src = scr + (size_t)ch * SCR_STRIDE;
            // scratch -> smem (grams + AKV/QKV slices)
            float4 gr = ld4(src + tid * 4);
            int ts = tid >> 3, ii = (tid & 7) * 2;
            float2 akv2 = *reinterpret_cast<const float2*>(src + 512  + ts * 64 + i0 + ii);
            float2 qkv2 = *reinterpret_cast<const float2*>(src + 1536 + ts * 64 + i0 + ii);

            size_t base = (((size_t)b * T_ + ch * DT_ + th * 8) * H_ + h) * C_ + cl;
            float rw[8], rq[8], rk[8], ra[8], rb[8], rv[8];
            #pragma unroll
            for (int r = 0; r < 8; r++) {
                size_t ix = base + (size_t)r * strT;
                rw[r] = gw[ix]; rq[r] = gq[ix]; rk[r] = gk[ix];
                ra[r] = ga[ix]; rb[r] = gb[ix];
                rv[r] = mine ? gv[ix] : 0.f;
            }
            st4(sGR + tid * 4, gr);
            *reinterpret_cast<float2*>(sAKV + ts * 16 + ii) = akv2;
            *reinterpret_cast<float2*>(sQKV + ts * 16 + ii) = qkv2;

            float wd[8]; float lp = 1.f;
            #pragma unroll
            for (int r = 0; r < 8; r++) { wd[r] = __expf(-__expf(rw[r])); lp *= wd[r]; }
            sLP[th][cl] = lp;
            __syncthreads();                       // bar1
            float incl = th ? sLP[0][cl] : 1.f;
            #pragma unroll
            for (int r = 0; r < 8; r++) {
                int t = th * 8 + r;
                float ip = incl; incl *= wd[r];
                float rinv = __fdividef(1.f, incl);
                int twd = tile_w(t, cl);
                sWQ[twd]  = rq[r] * incl;
                sWA[twd]  = ra[r] * ip;
                sKWI[twd] = rk[r] * rinv;
                sBWI[twd] = rb[r] * rinv;
                if (mine) sV[t * 16 + (cl & 15)] = rv[r];
            }
            if (th == 1) sFW[cl] = incl;
        }
        __syncthreads();                           // bar2

        // ===== abu = AKV + wa@S^T ; yp = QKV + wq@S^T =====
        float yp0, yp1;
        {
            const int t = tid >> 3, ip = tid & 7;
            const int il0 = 2 * ip, il1 = 2 * ip + 1;
            u64 aa0 = 0, aa1 = 0, ay0 = 0, ay1 = 0;
            #pragma unroll
            for (int j4 = 0; j4 < 16; j4++) {
                int tf = (((j4 ^ t) & 15) << 2);
                ulonglong2 A  = ldp(sWA + t * 64 + tf);
                ulonglong2 Q  = ldp(sWQ + t * 64 + tf);
                ulonglong2 S0 = ldp(sS + il0 * 64 + (((j4 ^ il0) & 15) << 2));
                ulonglong2 S1 = ldp(sS + il1 * 64 + (((j4 ^ il1) & 15) << 2));
                fma2(aa0, A.x, S0.x); fma2(aa0, A.y, S0.y);
                fma2(aa1, A.x, S1.x); fma2(aa1, A.y, S1.y);
                fma2(ay0, Q.x, S0.x); fma2(ay0, Q.y, S0.y);
                fma2(ay1, Q.x, S1.x); fma2(ay1, Q.y, S1.y);
            }
            float x, yv;
            un2(aa0, x, yv); float abu0 = x + yv;
            un2(aa1, x, yv); float abu1 = x + yv;
            un2(ay0, x, yv); yp0 = x + yv;
            un2(ay1, x, yv); yp1 = x + yv;
            float2 akv = *reinterpret_cast<const float2*>(sAKV + t * 16 + il0);
            float2 qkv = *reinterpret_cast<const float2*>(sQKV + t * 16 + il0);
            abu0 += akv.x; abu1 += akv.y;
            yp0  += qkv.x; yp1  += qkv.y;
            *reinterpret_cast<float2*>(sABU + t * 16 + il0) = make_float2(abu0, abu1);
        }
        __syncthreads();                           // bar3

        // ===== solve (I-ab) u = abu over 16 local columns =====
        if (tid < CI) {
            const int c = tid;
            float uu[DT_];
            #pragma unroll
            for (int t = 0; t < DT_; t++) uu[t] = sABU[t * 16 + c];
            #pragma unroll
            for (int t = 1; t < DT_; t++) {
                float a0 = uu[t], a1 = 0.f, a2 = 0.f, a3 = 0.f;
                const float* abr = sGR + t * 16;
                #pragma unroll
                for (int s4 = 0; 4 * s4 < t; s4++) {
                    float4 abq = ld4(abr + 4 * s4);
                    int s = 4 * s4;
                    if (s     < t) a0 += abq.x * uu[s];
                    if (s + 1 < t) a1 += abq.y * uu[s + 1];
                    if (s + 2 < t) a2 += abq.z * uu[s + 2];
                    if (s + 3 < t) a3 += abq.w * uu[s + 3];
                }
                uu[t] = (a0 + a1) + (a2 + a3);
            }
            #pragma unroll
            for (int t = 0; t < DT_; t++) sU[t * 16 + c] = uu[t];
        }
        __syncthreads();                           // bar4

        // ===== y out + state update =====
        {
            const int t = tid >> 3, ip = tid & 7;
            u64 y01 = pk2(yp0, yp1);
            #pragma unroll
            for (int s = 0; s < 16; s++) {
                float qb = sGR[256 + t * 16 + s];
                u64 u2 = *reinterpret_cast<const u64*>(sU + s * 16 + 2 * ip);
                fma2(y01, pk2(qb, qb), u2);
            }
            float o0, o1; un2(y01, o0, o1);
            size_t yb = (((size_t)b * T_ + ch * DT_ + t) * H_ + h) * C_ + i0 + 2 * ip;
            *reinterpret_cast<float2*>(gy + yb) = make_float2(o0, o1);
        }
        {
            const int ip2 = tid >> 4, jq = tid & 15;
            const int il0 = 2 * ip2, il1 = il0 + 1;
            u64 a00 = 0, a01 = 0, a10 = 0, a11 = 0;
            #pragma unroll
            for (int t = 0; t < DT_; t++) {
                float2 v2 = *reinterpret_cast<const float2*>(sV + t * 16 + il0);
                float2 u2 = *reinterpret_cast<const float2*>(sU + t * 16 + il0);
                int jf = (((jq ^ t) & 15) << 2);
                ulonglong2 K  = ldp(sKWI + t * 64 + jf);
                ulonglong2 Bv = ldp(sBWI + t * 64 + jf);
                u64 vx = pk2(v2.x, v2.x), vy = pk2(v2.y, v2.y);
                u64 ux = pk2(u2.x, u2.x), uy = pk2(u2.y, u2.y);
                fma2(a00, vx, K.x);  fma2(a01, vx, K.y);
                fma2(a10, vy, K.x);  fma2(a11, vy, K.y);
                fma2(a00, ux, Bv.x); fma2(a01, ux, Bv.y);
                fma2(a10, uy, Bv.x); fma2(a11, uy, Bv.y);
            }
            ulonglong2 FW = ldp(sFW + 4 * jq);
            float* sp0 = sS + il0 * 64 + (((jq ^ il0) & 15) << 2);
            float* sp1 = sS + il1 * 64 + (((jq ^ il1) & 15) << 2);
            ulonglong2 S0 = ldp(sp0), S1 = ldp(sp1);
            S0.x = mul2(add2(S0.x, a00), FW.x); S0.y = mul2(add2(S0.y, a01), FW.y);
            S1.x = mul2(add2(S1.x, a10), FW.x); S1.y = mul2(add2(S1.y, a11), FW.y);
            stp(sp0, S0); stp(sp1, S1);
        }
        __syncthreads();                           // bar5
    }
}

extern "C" void kernel_launch(void* const* d_in, const int* in_sizes, int n_in,
                              void* d_out, int out_size)
{
    const float* w  = (const float*)d_in[0];
    const float* q  = (const float*)d_in[1];
    const float* k  = (const float*)d_in[2];
    const float* v  = (const float*)d_in[3];
    const float* a  = (const float*)d_in[4];
    const float* b  = (const float*)d_in[5];
    const float* s0 = (const float*)d_in[6];
    float* y = (float*)d_out;

    cudaFuncSetAttribute(rwkv7_scan, cudaFuncAttributePreferredSharedMemoryCarveout, 100);

    rwkv7_pre<<<B_ * H_ * NT_, 128>>>(w, q, k, v, a, b);
    rwkv7_scan<<<B_ * H_ * SPLIT, 128>>>(w, q, k, v, a, b, s0, y);
}

// round 6
// speedup vs baseline: 1.1410x; 1.1410x over previous
#include <cuda_runtime.h>
#include <cstdint>

// RWKV7 chunked attention, B=4 T=2048 H=32 C=64 dT=16.
// 2 CTAs per (b,h), each owning 32 v-channels (i). 256 threads/CTA,
// 2 CTAs co-resident per SM -> two independent barrier domains.

#define B_ 4
#define T_ 2048
#define H_ 32
#define C_ 64
#define DT_ 16
#define NT_ 128
#define THREADS 256
#define CI 32              // channels per CTA

typedef unsigned long long u64;

// ---- static shared layout (float words) ----
#define OFF_WQ   0
#define OFF_WA   1024
#define OFF_KWI  2048
#define OFF_BWI  3072      // [16][64] each
#define OFF_V    4096      // [16][32]
#define OFF_U    4608
#define OFF_ABU  5120
#define OFF_AB   5632      // [16][16]
#define OFF_QB   5888
#define OFF_AKQK 6144      // [16][16] pairs (ak,qk)
#define OFF_LP   6656      // [4][64]
#define OFF_FW   6912      // [64]
#define OFF_ST   6976      // [32][64]
#define SMEM_WORDS (OFF_ST + 2048)   // 9024 floats = 36.1KB

// swizzles
__device__ __forceinline__ int tg(int t, int f)  { return t * 64 + (((f ^ t) & 15) << 2); }           // [16][64] group
__device__ __forceinline__ int tw(int t, int c)  { return t * 64 + ((((c >> 2) ^ t) & 15) << 2) + (c & 3); }
__device__ __forceinline__ int vg(int t, int f)  { return t * 32 + (((f ^ (t & 7)) & 7) << 2); }       // [16][32] group
__device__ __forceinline__ int vw(int t, int c)  { return t * 32 + ((((c >> 2) ^ (t & 7)) & 7) << 2) + (c & 3); }
__device__ __forceinline__ int sg(int r, int f)  { return r * 64 + (((f ^ (r >> 2)) & 15) << 2); }     // [32][64] group

__device__ __forceinline__ float4 ld4(const float* p) { return *reinterpret_cast<const float4*>(p); }
__device__ __forceinline__ void st4(float* p, float4 v) { *reinterpret_cast<float4*>(p) = v; }
__device__ __forceinline__ ulonglong2 ldp(const float* p) { return *reinterpret_cast<const ulonglong2*>(p); }
__device__ __forceinline__ void stp(float* p, ulonglong2 v) { *reinterpret_cast<ulonglong2*>(p) = v; }

__device__ __forceinline__ u64 pk2(float lo, float hi) {
    u64 r; asm("mov.b64 %0, {%1, %2};" : "=l"(r) : "f"(lo), "f"(hi)); return r;
}
__device__ __forceinline__ void un2(u64 v, float& lo, float& hi) {
    asm("mov.b64 {%0, %1}, %2;" : "=f"(lo), "=f"(hi) : "l"(v));
}
__device__ __forceinline__ void fma2(u64& d, u64 a, u64 b) {
    asm("fma.rn.f32x2 %0, %1, %2, %0;" : "+l"(d) : "l"(a), "l"(b));
}
__device__ __forceinline__ u64 add2(u64 a, u64 b) {
    u64 d; asm("add.rn.f32x2 %0, %1, %2;" : "=l"(d) : "l"(a), "l"(b)); return d;
}
__device__ __forceinline__ u64 mul2(u64 a, u64 b) {
    u64 d; asm("mul.rn.f32x2 %0, %1, %2;" : "=l"(d) : "l"(a), "l"(b)); return d;
}

__global__ __launch_bounds__(THREADS, 2)
void rwkv7_kernel(const float* __restrict__ gw, const float* __restrict__ gq,
                  const float* __restrict__ gk, const float* __restrict__ gv,
                  const float* __restrict__ ga, const float* __restrict__ gb,
                  const float* __restrict__ gs0, float* __restrict__ gy)
{
    __shared__ __align__(16) float sm[SMEM_WORDS];

    const int bid = blockIdx.x;
    const int bh  = bid >> 1;
    const int isp = bid & 1;
    const int b   = bh / H_;
    const int h   = bh % H_;
    const int i0c = isp * CI;
    const int tid = threadIdx.x;

    // stage mapping: 4 t-groups x 64 columns
    const int th = tid >> 6;       // 0..3, owns t = 4*th + r
    const int cl = tid & 63;
    const bool mine = (cl >= i0c) && (cl < i0c + CI);
    const int ci = cl - i0c;       // local channel if mine

    // X mapping (tid<128): t = tid>>3, i-quad iq = tid&7 (local i = 4*iq..+3)
    const int txm = tid >> 3;
    const int iq  = tid & 7;
    // Y mapping (tid>=128): g = tid-128
    const int g   = tid & 127;
    const int tgy = g >> 3, sby = g & 7;          // grams: (tgy, sby / sby+8)
    const int iqy = g >> 4, jq = g & 15;          // outer products: i-quad, j-quad

    // ---- init state slice: rows = local i 0..31 ----
    {
        const float* s0p = gs0 + (size_t)bh * 4096 + (size_t)i0c * 64;
        #pragma unroll
        for (int q4 = tid; q4 < 512; q4 += THREADS) {
            int row = q4 >> 4, f = q4 & 15;
            st4(sm + OFF_ST + sg(row, f), ld4(s0p + row * 64 + f * 4));
        }
    }

    const size_t strT = (size_t)H_ * C_;

    // prefetch chunk 0 (4 t-rows per thread)
    float rw[4], rq[4], rk[4], rv[4], ra[4], rb[4];
    {
        size_t base = (((size_t)b * T_ + 4 * th) * H_ + h) * C_ + cl;
        #pragma unroll
        for (int r = 0; r < 4; r++) {
            size_t ix = base + (size_t)r * strT;
            rw[r] = gw[ix]; rq[r] = gq[ix]; rk[r] = gk[ix];
            ra[r] = ga[ix]; rb[r] = gb[ix];
            rv[r] = mine ? gv[ix] : 0.f;
        }
    }
    __syncthreads();

    for (int ch = 0; ch < NT_; ch++) {
        const int t0 = ch * DT_;

        // ===== A: local decay products =====
        float wd[4];
        {
            float lp = 1.f;
            #pragma unroll
            for (int r = 0; r < 4; r++) { wd[r] = __expf(-__expf(rw[r])); lp *= wd[r]; }
            sm[OFF_LP + th * 64 + cl] = lp;
        }
        __syncthreads();

        // ===== B: prefix, scale, stage tiles; prefetch next =====
        {
            float pre = 1.f;
            #pragma unroll
            for (int gg = 0; gg < 3; gg++)
                if (gg < th) pre *= sm[OFF_LP + gg * 64 + cl];
            float incl = pre;
            #pragma unroll
            for (int r = 0; r < 4; r++) {
                int t = 4 * th + r;
                float ip = incl; incl *= wd[r];
                float rinv = __fdividef(1.f, incl);
                int twd = tw(t, cl);
                sm[OFF_WQ  + twd] = rq[r] * incl;
                sm[OFF_WA  + twd] = ra[r] * ip;
                sm[OFF_KWI + twd] = rk[r] * rinv;
                sm[OFF_BWI + twd] = rb[r] * rinv;
                if (mine) sm[OFF_V + vw(t, ci)] = rv[r];
            }
            if (th == 3) sm[OFF_FW + cl] = incl;
        }
        if (ch + 1 < NT_) {
            size_t base = (((size_t)b * T_ + (t0 + DT_) + 4 * th) * H_ + h) * C_ + cl;
            #pragma unroll
            for (int r = 0; r < 4; r++) {
                size_t ix = base + (size_t)r * strT;
                rw[r] = gw[ix]; rq[r] = gq[ix]; rk[r] = gk[ix];
                ra[r] = ga[ix]; rb[r] = gb[ix];
                rv[r] = mine ? gv[ix] : 0.f;
            }
        }
        __syncthreads();

        float yp[4];       // X y-partials
        u64  ayp[4];       // X packed (abu, yp)
        u64  accY[4][2];   // Y state-update accumulators

        // ===== I3: X = state GEMM; Y = grams =====
        if (tid < 128) {
            u64 aa2[4] = {0,0,0,0}, ay2[4] = {0,0,0,0};
            #pragma unroll
            for (int j4 = 0; j4 < 16; j4++) {
                ulonglong2 A = ldp(sm + OFF_WA + tg(txm, j4));
                ulonglong2 Q = ldp(sm + OFF_WQ + tg(txm, j4));
                #pragma unroll
                for (int rr = 0; rr < 4; rr++) {
                    ulonglong2 S = ldp(sm + OFF_ST + sg(4 * iq + rr, j4));
                    fma2(aa2[rr], A.x, S.x); fma2(aa2[rr], A.y, S.y);
                    fma2(ay2[rr], Q.x, S.x); fma2(ay2[rr], Q.y, S.y);
                }
            }
            #pragma unroll
            for (int rr = 0; rr < 4; rr++) {
                float l0, h0, l1, h1;
                un2(aa2[rr], l0, h0); un2(ay2[rr], l1, h1);
                ayp[rr] = pk2(l0 + h0, l1 + h1);
            }
        } else {
            #pragma unroll
            for (int sh = 0; sh < 2; sh++) {
                const int s = sby + 8 * sh;
                u64 ab2 = 0, ak2 = 0, qb2 = 0, qk2 = 0;
                #pragma unroll
                for (int c4 = 0; c4 < 16; c4++) {
                    ulonglong2 A  = ldp(sm + OFF_WA  + tg(tgy, c4));
                    ulonglong2 Q  = ldp(sm + OFF_WQ  + tg(tgy, c4));
                    ulonglong2 Bv = ldp(sm + OFF_BWI + tg(s, c4));
                    ulonglong2 Kv = ldp(sm + OFF_KWI + tg(s, c4));
                    fma2(ab2, A.x, Bv.x); fma2(ab2, A.y, Bv.y);
                    fma2(ak2, A.x, Kv.x); fma2(ak2, A.y, Kv.y);
                    fma2(qb2, Q.x, Bv.x); fma2(qb2, Q.y, Bv.y);
                    fma2(qk2, Q.x, Kv.x); fma2(qk2, Q.y, Kv.y);
                }
                float l, hh, ab, ak, qb, qk;
                un2(ab2, l, hh); ab = l + hh;
                un2(ak2, l, hh); ak = l + hh;
                un2(qb2, l, hh); qb = l + hh;
                un2(qk2, l, hh); qk = l + hh;
                float ms = (tgy > s)  ? 1.f : 0.f;
                float mi = (tgy >= s) ? 1.f : 0.f;
                sm[OFF_AB + tgy * 16 + s] = ab * ms;
                sm[OFF_QB + tgy * 16 + s] = qb * mi;
                *reinterpret_cast<u64*>(sm + OFF_AKQK + (tgy * 16 + s) * 2) =
                    pk2(ak * ms, qk * mi);
            }
        }
        __syncthreads();   // bar3: grams ready

        // ===== I4: X = (ak,qk)@v -> abu; Y = accv = v^T kwi =====
        if (tid < 128) {
            #pragma unroll
            for (int s2 = 0; s2 < 8; s2++) {
                ulonglong2 ak2 = ldp(sm + OFF_AKQK + (txm * 16 + 2 * s2) * 2);
                float4 v4a = ld4(sm + OFF_V + vg(2 * s2,     iq));
                float4 v4b = ld4(sm + OFF_V + vg(2 * s2 + 1, iq));
                fma2(ayp[0], ak2.x, pk2(v4a.x, v4a.x));
                fma2(ayp[1], ak2.x, pk2(v4a.y, v4a.y));
                fma2(ayp[2], ak2.x, pk2(v4a.z, v4a.z));
                fma2(ayp[3], ak2.x, pk2(v4a.w, v4a.w));
                fma2(ayp[0], ak2.y, pk2(v4b.x, v4b.x));
                fma2(ayp[1], ak2.y, pk2(v4b.y, v4b.y));
                fma2(ayp[2], ak2.y, pk2(v4b.z, v4b.z));
                fma2(ayp[3], ak2.y, pk2(v4b.w, v4b.w));
            }
            float abu[4];
            #pragma unroll
            for (int rr = 0; rr < 4; rr++) un2(ayp[rr], abu[rr], yp[rr]);
            st4(sm + OFF_ABU + vg(txm, iq),
                make_float4(abu[0], abu[1], abu[2], abu[3]));
        } else {
            #pragma unroll
            for (int rr = 0; rr < 4; rr++) { accY[rr][0] = 0; accY[rr][1] = 0; }
            #pragma unroll
            for (int t = 0; t < DT_; t++) {
                float4 v4 = ld4(sm + OFF_V + vg(t, iqy));
                ulonglong2 K2 = ldp(sm + OFF_KWI + tg(t, jq));
                u64 v0 = pk2(v4.x, v4.x), v1 = pk2(v4.y, v4.y);
                u64 v2 = pk2(v4.z, v4.z), v3 = pk2(v4.w, v4.w);
                fma2(accY[0][0], v0, K2.x); fma2(accY[0][1], v0, K2.y);
                fma2(accY[1][0], v1, K2.x); fma2(accY[1][1], v1, K2.y);
                fma2(accY[2][0], v2, K2.x); fma2(accY[2][1], v2, K2.y);
                fma2(accY[3][0], v3, K2.x); fma2(accY[3][1], v3, K2.y);
            }
        }
        __syncthreads();   // bar4: abu complete

        // ===== solve (I-ab) u = abu over 32 local columns (1 warp) =====
        if (tid < CI) {
            const int c = tid;
            float uu[DT_];
            #pragma unroll
            for (int t = 0; t < DT_; t++) uu[t] = sm[OFF_ABU + vw(t, c)];
            #pragma unroll
            for (int t = 1; t < DT_; t++) {
                float a0 = uu[t], a1 = 0.f, a2 = 0.f, a3 = 0.f;
                const float* abr = sm + OFF_AB + t * 16;
                #pragma unroll
                for (int s4 = 0; 4 * s4 < t; s4++) {
                    float4 abq = ld4(abr + 4 * s4);
                    int s = 4 * s4;
                    if (s     < t) a0 += abq.x * uu[s];
                    if (s + 1 < t) a1 += abq.y * uu[s + 1];
                    if (s + 2 < t) a2 += abq.z * uu[s + 2];
                    if (s + 3 < t) a3 += abq.w * uu[s + 3];
                }
                uu[t] = (a0 + a1) + (a2 + a3);
            }
            #pragma unroll
            for (int t = 0; t < DT_; t++) sm[OFF_U + vw(t, c)] = uu[t];
        }
        __syncthreads();   // bar5: u ready

        // ===== I6: X = y out; Y = accu + state update =====
        if (tid < 128) {
            float4 qbr[4];
            #pragma unroll
            for (int r = 0; r < 4; r++) qbr[r] = ld4(sm + OFF_QB + txm * 16 + 4 * r);
            u64 y01 = pk2(yp[0], yp[1]);
            u64 y23 = pk2(yp[2], yp[3]);
            #pragma unroll
            for (int s = 0; s < 16; s++) {
                float qbs = (s & 2) ? ((s & 1) ? qbr[s >> 2].w : qbr[s >> 2].z)
                                    : ((s & 1) ? qbr[s >> 2].y : qbr[s >> 2].x);
                ulonglong2 U2 = ldp(sm + OFF_U + vg(s, iq));
                u64 q2 = pk2(qbs, qbs);
                fma2(y01, q2, U2.x);
                fma2(y23, q2, U2.y);
            }
            float o0, o1, o2, o3;
            un2(y01, o0, o1); un2(y23, o2, o3);
            size_t yb = (((size_t)b * T_ + t0 + txm) * H_ + h) * C_ + i0c + 4 * iq;
            __stcs(reinterpret_cast<float4*>(gy + yb), make_float4(o0, o1, o2, o3));
        } else {
            #pragma unroll
            for (int t = 0; t < DT_; t++) {
                float4 u4 = ld4(sm + OFF_U + vg(t, iqy));
                ulonglong2 B2 = ldp(sm + OFF_BWI + tg(t, jq));
                u64 u0 = pk2(u4.x, u4.x), u1 = pk2(u4.y, u4.y);
                u64 u2 = pk2(u4.z, u4.z), u3 = pk2(u4.w, u4.w);
                fma2(accY[0][0], u0, B2.x); fma2(accY[0][1], u0, B2.y);
                fma2(accY[1][0], u1, B2.x); fma2(accY[1][1], u1, B2.y);
                fma2(accY[2][0], u2, B2.x); fma2(accY[2][1], u2, B2.y);
                fma2(accY[3][0], u3, B2.x); fma2(accY[3][1], u3, B2.y);
            }
            ulonglong2 FWp = ldp(sm + OFF_FW + 4 * jq);
            #pragma unroll
            for (int rr = 0; rr < 4; rr++) {
                float* sp = sm + OFF_ST + sg(4 * iqy + rr, jq);
                ulonglong2 S = ldp(sp);
                S.x = mul2(add2(S.x, accY[rr][0]), FWp.x);
                S.y = mul2(add2(S.y, accY[rr][1]), FWp.y);
                stp(sp, S);
            }
        }
        __syncthreads();   // bar6: state updated
    }
}

extern "C" void kernel_launch(void* const* d_in, const int* in_sizes, int n_in,
                              void* d_out, int out_size)
{
    const float* w  = (const float*)d_in[0];
    const float* q  = (const float*)d_in[1];
    const float* k  = (const float*)d_in[2];
    const float* v  = (const float*)d_in[3];
    const float* a  = (const float*)d_in[4];
    const float* b  = (const float*)d_in[5];
    const float* s0 = (const float*)d_in[6];
    float* y = (float*)d_out;

    rwkv7_kernel<<<B_ * H_ * 2, THREADS>>>(w, q, k, v, a, b, s0, y);
}

// round 7
// speedup vs baseline: 2.0594x; 1.8050x over previous
#include <cuda_runtime.h>
#include <cstdint>

// RWKV7 chunked attention, B=4 T=2048 H=32 C=64 dT=16.
// One CTA (512 thr) per (b,h). Software pipeline:
//   producer warps 8-15: chunk ch+1 stage + grams + AKV/QKV  (state-independent)
//   consumer warps 0-7 : chunk ch   state GEMM + solve + y + state update
// Double-buffered smem handoff, named barriers per group, 1 syncthreads/chunk.

#define B_ 4
#define T_ 2048
#define H_ 32
#define C_ 64
#define DT_ 16
#define NT_ 128
#define THREADS 512

typedef unsigned long long u64;

// ---- shared layout (float words) ----
#define OFF_S    0          // [64][64] sg swizzle
#define OFF_U    4096       // [16][64] tg swizzle
#define OFF_ABU  5120       // [16][64]
#define OFF_AKQK 6144       // [16][16] (ak,qk) pairs, producer-local
#define OFF_LPP  6656       // [4][64] producer prefix scratch
#define OFF_BUF  6912
#define BUF_STRIDE 7744
// offsets within one buffer:
#define BWA  0
#define BWQ  1024
#define BKWI 2048
#define BBWI 3072
#define BV   4096
#define BAKV 5120
#define BQKV 6144
#define BAB  7168
#define BQB  7424
#define BFW  7680
#define SMEM_WORDS (OFF_BUF + 2 * BUF_STRIDE)   // 22400 floats = 89.6 KB
#define SMEM_BYTES (SMEM_WORDS * 4)

#define BARC() asm volatile("bar.sync 1, 256;" ::: "memory")   // consumer group
#define BARP() asm volatile("bar.sync 2, 256;" ::: "memory")   // producer group

// xor swizzles
__device__ __forceinline__ int tg(int t, int f)  { return t * 64 + (((f ^ t) & 15) << 2); }
__device__ __forceinline__ int tw(int t, int c)  { return t * 64 + ((((c >> 2) ^ t) & 15) << 2) + (c & 3); }
__device__ __forceinline__ int sg(int r, int f)  { return r * 64 + (((f ^ (r >> 2)) & 15) << 2); }

__device__ __forceinline__ float4 ld4(const float* p) { return *reinterpret_cast<const float4*>(p); }
__device__ __forceinline__ void st4(float* p, float4 v) { *reinterpret_cast<float4*>(p) = v; }
__device__ __forceinline__ ulonglong2 ldp(const float* p) { return *reinterpret_cast<const ulonglong2*>(p); }
__device__ __forceinline__ void stp(float* p, ulonglong2 v) { *reinterpret_cast<ulonglong2*>(p) = v; }

__device__ __forceinline__ u64 pk2(float lo, float hi) {
    u64 r; asm("mov.b64 %0, {%1, %2};" : "=l"(r) : "f"(lo), "f"(hi)); return r;
}
__device__ __forceinline__ void un2(u64 v, float& lo, float& hi) {
    asm("mov.b64 {%0, %1}, %2;" : "=f"(lo), "=f"(hi) : "l"(v));
}
__device__ __forceinline__ void fma2(u64& d, u64 a, u64 b) {
    asm("fma.rn.f32x2 %0, %1, %2, %0;" : "+l"(d) : "l"(a), "l"(b));
}
__device__ __forceinline__ u64 add2(u64 a, u64 b) {
    u64 d; asm("add.rn.f32x2 %0, %1, %2;" : "=l"(d) : "l"(a), "l"(b)); return d;
}
__device__ __forceinline__ u64 mul2(u64 a, u64 b) {
    u64 d; asm("mul.rn.f32x2 %0, %1, %2;" : "=l"(d) : "l"(a), "l"(b)); return d;
}

// ---------- producer: stage chunk cp into buffer q ----------
__device__ __forceinline__ void produce(
    float* __restrict__ sm, float* __restrict__ buf,
    const float* __restrict__ gw, const float* __restrict__ gq,
    const float* __restrict__ gk, const float* __restrict__ gv,
    const float* __restrict__ ga, const float* __restrict__ gb,
    int b, int h, int cp, int pt)
{
    const int th = pt >> 6;        // 0..3, owns t = 4*th + r
    const int cl = pt & 63;
    const size_t strT = (size_t)H_ * C_;

    // load + decay + stage
    {
        size_t base = (((size_t)b * T_ + cp * DT_ + 4 * th) * H_ + h) * C_ + cl;
        float rw[4], rq[4], rk[4], rv[4], ra[4], rb[4];
        #pragma unroll
        for (int r = 0; r < 4; r++) {
            size_t ix = base + (size_t)r * strT;
            rw[r] = gw[ix]; rq[r] = gq[ix]; rk[r] = gk[ix];
            rv[r] = gv[ix]; ra[r] = ga[ix]; rb[r] = gb[ix];
        }
        float wd[4]; float lp = 1.f;
        #pragma unroll
        for (int r = 0; r < 4; r++) { wd[r] = __expf(-__expf(rw[r])); lp *= wd[r]; }
        sm[OFF_LPP + th * 64 + cl] = lp;
        BARP();
        float incl = 1.f;
        #pragma unroll
        for (int gg = 0; gg < 3; gg++)
            if (gg < th) incl *= sm[OFF_LPP + gg * 64 + cl];
        #pragma unroll
        for (int r = 0; r < 4; r++) {
            int t = 4 * th + r;
            float ip = incl; incl *= wd[r];
            float rinv = __fdividef(1.f, incl);
            int twd = tw(t, cl);
            buf[BWQ  + twd] = rq[r] * incl;
            buf[BWA  + twd] = ra[r] * ip;
            buf[BKWI + twd] = rk[r] * rinv;
            buf[BBWI + twd] = rb[r] * rinv;
            buf[BV   + twd] = rv[r];
        }
        if (th == 3) buf[BFW + cl] = incl;
    }
    BARP();

    // grams: (t, s) one thread each
    {
        const int t = pt >> 4, s = pt & 15;
        u64 ab2 = 0, ak2 = 0, qb2 = 0, qk2 = 0;
        #pragma unroll
        for (int c4 = 0; c4 < 16; c4++) {
            ulonglong2 A  = ldp(buf + BWA  + tg(t, c4));
            ulonglong2 Q  = ldp(buf + BWQ  + tg(t, c4));
            ulonglong2 Bv = ldp(buf + BBWI + tg(s, c4));
            ulonglong2 Kv = ldp(buf + BKWI + tg(s, c4));
            fma2(ab2, A.x, Bv.x); fma2(ab2, A.y, Bv.y);
            fma2(ak2, A.x, Kv.x); fma2(ak2, A.y, Kv.y);
            fma2(qb2, Q.x, Bv.x); fma2(qb2, Q.y, Bv.y);
            fma2(qk2, Q.x, Kv.x); fma2(qk2, Q.y, Kv.y);
        }
        float l, hh, ab, ak, qb, qk;
        un2(ab2, l, hh); ab = l + hh;
        un2(ak2, l, hh); ak = l + hh;
        un2(qb2, l, hh); qb = l + hh;
        un2(qk2, l, hh); qk = l + hh;
        float ms = (t > s)  ? 1.f : 0.f;
        float mi = (t >= s) ? 1.f : 0.f;
        buf[BAB + t * 16 + s] = ab * ms;
        buf[BQB + t * 16 + s] = qb * mi;
        *reinterpret_cast<u64*>(sm + OFF_AKQK + (t * 16 + s) * 2) = pk2(ak * ms, qk * mi);
    }
    BARP();

    // AKV = ak@v, QKV = qk@v
    {
        const int t = pt >> 4, iq = pt & 15;
        u64 acc[4] = {0, 0, 0, 0};
        #pragma unroll
        for (int s = 0; s < 16; s++) {
            u64 akqk = *reinterpret_cast<const u64*>(sm + OFF_AKQK + (t * 16 + s) * 2);
            float4 v4 = ld4(buf + BV + tg(s, iq));
            fma2(acc[0], akqk, pk2(v4.x, v4.x));
            fma2(acc[1], akqk, pk2(v4.y, v4.y));
            fma2(acc[2], akqk, pk2(v4.z, v4.z));
            fma2(acc[3], akqk, pk2(v4.w, v4.w));
        }
        float akv[4], qkv[4];
        #pragma unroll
        for (int r = 0; r < 4; r++) un2(acc[r], akv[r], qkv[r]);
        st4(buf + BAKV + tg(t, iq), make_float4(akv[0], akv[1], akv[2], akv[3]));
        st4(buf + BQKV + tg(t, iq), make_float4(qkv[0], qkv[1], qkv[2], qkv[3]));
    }
}

__global__ __launch_bounds__(THREADS, 1)
void rwkv7_kernel(const float* __restrict__ gw, const float* __restrict__ gq,
                  const float* __restrict__ gk, const float* __restrict__ gv,
                  const float* __restrict__ ga, const float* __restrict__ gb,
                  const float* __restrict__ gs0, float* __restrict__ gy)
{
    extern __shared__ float sm[];

    const int bh  = blockIdx.x;
    const int b   = bh / H_;
    const int h   = bh % H_;
    const int tid = threadIdx.x;
    const bool is_prod = tid >= 256;
    const int pt = tid & 255;

    // consumer GEMM/y mapping: warp covers 4 t x 8 i-quads
    const int w   = pt >> 5;
    const int tx  = (w & 3) * 4 + ((pt >> 3) & 3);
    const int iq  = ((w >> 2) & 1) * 8 + (pt & 7);
    // consumer accv/update mapping
    const int iq2 = pt >> 4;
    const int jq  = pt & 15;

    // ---- bootstrap ----
    if (is_prod) {
        produce(sm, sm + OFF_BUF, gw, gq, gk, gv, ga, gb, b, h, 0, pt);
    } else {
        const float* s0p = gs0 + (size_t)bh * 4096;
        #pragma unroll
        for (int q4 = pt; q4 < 1024; q4 += 256) {
            int row = q4 >> 4, f = q4 & 15;
            st4(sm + OFF_S + sg(row, f), ld4(s0p + row * 64 + f * 4));
        }
    }
    __syncthreads();

    for (int ch = 0; ch < NT_; ch++) {
        const int p = ch & 1;

        if (is_prod) {
            if (ch + 1 < NT_)
                produce(sm, sm + OFF_BUF + (p ^ 1) * BUF_STRIDE,
                        gw, gq, gk, gv, ga, gb, b, h, ch + 1, pt);
        } else {
            float* buf = sm + OFF_BUF + p * BUF_STRIDE;

            // ===== state GEMM: aa = wa@S^T, ay = wq@S^T =====
            float yp[4];
            {
                u64 aa2[4] = {0,0,0,0}, ay2[4] = {0,0,0,0};
                #pragma unroll
                for (int j4 = 0; j4 < 16; j4++) {
                    ulonglong2 A = ldp(buf + BWA + tg(tx, j4));
                    ulonglong2 Q = ldp(buf + BWQ + tg(tx, j4));
                    #pragma unroll
                    for (int r = 0; r < 4; r++) {
                        ulonglong2 S = ldp(sm + OFF_S + sg(4 * iq + r, j4));
                        fma2(aa2[r], A.x, S.x); fma2(aa2[r], A.y, S.y);
                        fma2(ay2[r], Q.x, S.x); fma2(ay2[r], Q.y, S.y);
                    }
                }
                float4 akv4 = ld4(buf + BAKV + tg(tx, iq));
                float4 qkv4 = ld4(buf + BQKV + tg(tx, iq));
                float abu[4];
                float l0, h0, l1, h1;
                un2(aa2[0], l0, h0); un2(ay2[0], l1, h1);
                abu[0] = l0 + h0 + akv4.x; yp[0] = l1 + h1 + qkv4.x;
                un2(aa2[1], l0, h0); un2(ay2[1], l1, h1);
                abu[1] = l0 + h0 + akv4.y; yp[1] = l1 + h1 + qkv4.y;
                un2(aa2[2], l0, h0); un2(ay2[2], l1, h1);
                abu[2] = l0 + h0 + akv4.z; yp[2] = l1 + h1 + qkv4.z;
                un2(aa2[3], l0, h0); un2(ay2[3], l1, h1);
                abu[3] = l0 + h0 + akv4.w; yp[3] = l1 + h1 + qkv4.w;
                st4(sm + OFF_ABU + tg(tx, iq),
                    make_float4(abu[0], abu[1], abu[2], abu[3]));
            }

            // ===== accv = v^T kwi (4x4 tile per thread) =====
            u64 accR[4][2];
            {
                #pragma unroll
                for (int r = 0; r < 4; r++) { accR[r][0] = 0; accR[r][1] = 0; }
                #pragma unroll
                for (int t = 0; t < DT_; t++) {
                    float4 v4 = ld4(buf + BV + tg(t, iq2));
                    ulonglong2 K2 = ldp(buf + BKWI + tg(t, jq));
                    u64 v0 = pk2(v4.x, v4.x), v1 = pk2(v4.y, v4.y);
                    u64 v2 = pk2(v4.z, v4.z), v3 = pk2(v4.w, v4.w);
                    fma2(accR[0][0], v0, K2.x); fma2(accR[0][1], v0, K2.y);
                    fma2(accR[1][0], v1, K2.x); fma2(accR[1][1], v1, K2.y);
                    fma2(accR[2][0], v2, K2.x); fma2(accR[2][1], v2, K2.y);
                    fma2(accR[3][0], v3, K2.x); fma2(accR[3][1], v3, K2.y);
                }
            }
            BARC();   // abu complete

            // ===== solve (I-ab) u = abu (64 columns, 2 warps) =====
            if (pt < 64) {
                const int c = pt;
                float uu[DT_];
                #pragma unroll
                for (int t = 0; t < DT_; t++) uu[t] = sm[OFF_ABU + tw(t, c)];
                #pragma unroll
                for (int t = 1; t < DT_; t++) {
                    float a0 = uu[t], a1 = 0.f, a2 = 0.f, a3 = 0.f;
                    const float* abr = buf + BAB + t * 16;
                    #pragma unroll
                    for (int s4 = 0; 4 * s4 < t; s4++) {
                        float4 abq = ld4(abr + 4 * s4);
                        int s = 4 * s4;
                        if (s     < t) a0 += abq.x * uu[s];
                        if (s + 1 < t) a1 += abq.y * uu[s + 1];
                        if (s + 2 < t) a2 += abq.z * uu[s + 2];
                        if (s + 3 < t) a3 += abq.w * uu[s + 3];
                    }
                    uu[t] = (a0 + a1) + (a2 + a3);
                }
                #pragma unroll
                for (int t = 0; t < DT_; t++) sm[OFF_U + tw(t, c)] = uu[t];
            }
            BARC();   // u ready

            // ===== y = yp + qb@u =====
            {
                float4 qbr[4];
                #pragma unroll
                for (int r = 0; r < 4; r++) qbr[r] = ld4(buf + BQB + tx * 16 + 4 * r);
                u64 y01 = pk2(yp[0], yp[1]);
                u64 y23 = pk2(yp[2], yp[3]);
                #pragma unroll
                for (int s = 0; s < 16; s++) {
                    float qbs = (s & 2) ? ((s & 1) ? qbr[s >> 2].w : qbr[s >> 2].z)
                                        : ((s & 1) ? qbr[s >> 2].y : qbr[s >> 2].x);
                    ulonglong2 U2 = ldp(sm + OFF_U + tg(s, iq));
                    u64 q2 = pk2(qbs, qbs);
                    fma2(y01, q2, U2.x);
                    fma2(y23, q2, U2.y);
                }
                float o0, o1, o2, o3;
                un2(y01, o0, o1); un2(y23, o2, o3);
                size_t yb = (((size_t)b * T_ + ch * DT_ + tx) * H_ + h) * C_ + 4 * iq;
                __stcs(reinterpret_cast<float4*>(gy + yb), make_float4(o0, o1, o2, o3));
            }

            // ===== state update: S = (S + accv + u^T bwi) * fw =====
            {
                #pragma unroll
                for (int t = 0; t < DT_; t++) {
                    float4 u4 = ld4(sm + OFF_U + tg(t, iq2));
                    ulonglong2 B2 = ldp(buf + BBWI + tg(t, jq));
                    u64 u0 = pk2(u4.x, u4.x), u1 = pk2(u4.y, u4.y);
                    u64 u2 = pk2(u4.z, u4.z), u3 = pk2(u4.w, u4.w);
                    fma2(accR[0][0], u0, B2.x); fma2(accR[0][1], u0, B2.y);
                    fma2(accR[1][0], u1, B2.x); fma2(accR[1][1], u1, B2.y);
                    fma2(accR[2][0], u2, B2.x); fma2(accR[2][1], u2, B2.y);
                    fma2(accR[3][0], u3, B2.x); fma2(accR[3][1], u3, B2.y);
                }
                ulonglong2 FWp = ldp(buf + BFW + 4 * jq);
                #pragma unroll
                for (int r = 0; r < 4; r++) {
                    float* sp = sm + OFF_S + sg(4 * iq2 + r, jq);
                    ulonglong2 S = ldp(sp);
                    S.x = mul2(add2(S.x, accR[r][0]), FWp.x);
                    S.y = mul2(add2(S.y, accR[r][1]), FWp.y);
                    stp(sp, S);
                }
            }
        }
        __syncthreads();   // buffer handoff
    }
}

extern "C" void kernel_launch(void* const* d_in, const int* in_sizes, int n_in,
                              void* d_out, int out_size)
{
    const float* w  = (const float*)d_in[0];
    const float* q  = (const float*)d_in[1];
    const float* k  = (const float*)d_in[2];
    const float* v  = (const float*)d_in[3];
    const float* a  = (const float*)d_in[4];
    const float* b  = (const float*)d_in[5];
    const float* s0 = (const float*)d_in[6];
    float* y = (float*)d_out;

    cudaFuncSetAttribute(rwkv7_kernel, cudaFuncAttributeMaxDynamicSharedMemorySize, SMEM_BYTES);
    rwkv7_kernel<<<B_ * H_, THREADS, SMEM_BYTES>>>(w, q, k, v, a, b, s0, y);
}